// round 14
// baseline (speedup 1.0000x reference)
#include <cuda_runtime.h>
#include <math.h>

#define BB 32
#define SS 2048
#define DD 1024
#define ROWS 64
#define CHUNKS (SS / ROWS)      // 32 blocks per batch
#define NBLK (BB * CHUNKS)      // 1024 streaming blocks; +1 spinner block
#define BETA_F 0.1f
#define RHO_F 1.0f
#define CNT_STRIDE 32           // pad counters to 128B

// Deterministic per-block partials, packed: .x = <e1,w>, .y = <e2,w>
__device__ float2 g_p[NBLK];
// Per-batch completion counters (zero at load; spinner resets each replay)
__device__ unsigned int g_cnt[BB * CNT_STRIDE];

__global__ void __launch_bounds__(256, 8) wdpo_kernel(const float* __restrict__ e1,
                                                      const float* __restrict__ e2,
                                                      const float* __restrict__ w,
                                                      const float* __restrict__ lp1ref,
                                                      const float* __restrict__ lp2ref,
                                                      const float* __restrict__ pref,
                                                      float* __restrict__ out) {
    const int t   = threadIdx.x;
    const int blk = blockIdx.x;
    const int lane = t & 31, wid = t >> 5;

    __shared__ float sh1[8], sh2[8];

    if (blk < NBLK) {
        // ================= hot streaming path (R9/R12 body, measured ~7 TB/s) =====
        const int b     = blk >> 5;             // / CHUNKS
        const int chunk = blk & (CHUNKS - 1);

        const float4 w4 = reinterpret_cast<const float4*>(w)[t];

        const size_t base = ((size_t)b * SS + (size_t)chunk * ROWS) * DD + 4 * (size_t)t;
        const float4* __restrict__ p1 = reinterpret_cast<const float4*>(e1 + base);
        const float4* __restrict__ p2 = reinterpret_cast<const float4*>(e2 + base);

        float s1 = 0.f, s2 = 0.f;
#pragma unroll 8
        for (int r = 0; r < ROWS; r++) {
            const float4 a = p1[(size_t)r * (DD / 4)];
            const float4 c = p2[(size_t)r * (DD / 4)];
            s1 += a.x * w4.x + a.y * w4.y + a.z * w4.z + a.w * w4.w;
            s2 += c.x * w4.x + c.y * w4.y + c.z * w4.z + c.w * w4.w;
        }

#pragma unroll
        for (int o = 16; o; o >>= 1) {
            s1 += __shfl_down_sync(0xffffffffu, s1, o);
            s2 += __shfl_down_sync(0xffffffffu, s2, o);
        }
        if (lane == 0) { sh1[wid] = s1; sh2[wid] = s2; }
        __syncthreads();
        if (wid == 0) {
            s1 = (lane < 8) ? sh1[lane] : 0.f;
            s2 = (lane < 8) ? sh2[lane] : 0.f;
#pragma unroll
            for (int o = 4; o; o >>= 1) {
                s1 += __shfl_down_sync(0xffffffffu, s1, o);
                s2 += __shfl_down_sync(0xffffffffu, s2, o);
            }
            if (lane == 0) {
                // single-thread release + per-batch flag (R9-measured-fast pattern)
                g_p[blk] = make_float2(s1, s2);
                __threadfence();
                atomicAdd(&g_cnt[b * CNT_STRIDE], 1u);
            }
        }
        return;
    }

    // ================= spinner block (cold path, runs once, concurrent) =========
    __shared__ float s_ind[BB];
    __shared__ float s_c2[BB];
    __shared__ float s_wsq;

    // ||w||^2 while the streamers run — zero extra DRAM pressure (w is 4KB, L2-hot)
    {
        const float4 wv = reinterpret_cast<const float4*>(w)[t];
        float v = wv.x * wv.x + wv.y * wv.y + wv.z * wv.z + wv.w * wv.w;
#pragma unroll
        for (int o = 16; o; o >>= 1) v += __shfl_down_sync(0xffffffffu, v, o);
        if (lane == 0) sh1[wid] = v;
        __syncthreads();
        if (t == 0) {
            float a = 0.f;
#pragma unroll
            for (int i = 0; i < 8; i++) a += sh1[i];
            s_wsq = a;
        }
    }

    // warp `wid` handles batches wid*4 .. wid*4+3: wait for each batch's 32
    // flags, then fold its 32 partials (one float2 per lane). Early batches
    // fold while later ones still stream.
#pragma unroll
    for (int j = 0; j < 4; j++) {
        const int bb = wid * 4 + j;
        unsigned int* cnt = &g_cnt[bb * CNT_STRIDE];
        if (lane == 0) {
            while (atomicAdd(cnt, 0u) < (unsigned)CHUNKS) __nanosleep(128);
        }
        __syncwarp();
        __threadfence();                            // acquire partials

        const float2 pp = __ldcg(&g_p[bb * CHUNKS + lane]);
        float s1 = pp.x, s2 = pp.y;
#pragma unroll
        for (int o = 16; o; o >>= 1) {
            s1 += __shfl_down_sync(0xffffffffu, s1, o);
            s2 += __shfl_down_sync(0xffffffffu, s2, o);
        }
        if (lane == 0) {
            const float h = (s1 - lp1ref[bb]) - (s2 - lp2ref[bb]);
            const float z = BETA_F * h;
            const float p = pref[bb];
            // stable softplus: softplus(x) = max(x,0) + log1p(exp(-|x|))
            const float lp = log1pf(expf(-fabsf(z)));
            const float sp_pos = fmaxf(z, 0.f) + lp;   // softplus(z)  = l2
            const float sp_neg = fmaxf(-z, 0.f) + lp;  // softplus(-z) = l1
            s_ind[bb] = p * sp_neg + (1.f - p) * sp_pos;
            const float sig = 1.f / (1.f + expf(-z));
            const float c = BETA_F * (sig - p);
            s_c2[bb] = c * c;                           // wsq factored out
            *cnt = 0u;                                  // reset for next replay
        }
    }
    __syncthreads();
    if (wid == 0) {
        float i  = s_ind[lane];
        float c2 = s_c2[lane];
#pragma unroll
        for (int o = 16; o; o >>= 1) {
            i  += __shfl_down_sync(0xffffffffu, i, o);
            c2 += __shfl_down_sync(0xffffffffu, c2, o);
        }
        if (lane == 0) {
            // mean(gns) = 2*S*wsq*mean(c^2)
            out[0] = i * (1.f / (float)BB)
                   + RHO_F * sqrtf(2.f * (float)SS * s_wsq * c2 * (1.f / (float)BB));
        }
    }
}

extern "C" void kernel_launch(void* const* d_in, const int* in_sizes, int n_in,
                              void* d_out, int out_size) {
    const float* e1     = (const float*)d_in[0];  // emb_a1 (B,S,D)
    const float* e2     = (const float*)d_in[1];  // emb_a2 (B,S,D)
    const float* w      = (const float*)d_in[2];  // w (D,)
    const float* lp1ref = (const float*)d_in[3];  // log_prob_a1_ref (B,)
    const float* lp2ref = (const float*)d_in[4];  // log_prob_a2_ref (B,)
    const float* pref   = (const float*)d_in[5];  // preference (B,)
    float* out          = (float*)d_out;

    // 1024 streaming blocks + 1 spinner block — all resident in one wave
    // (1025 <= 148 SMs * 8 CTAs), so the spin cannot deadlock.
    wdpo_kernel<<<NBLK + 1, 256>>>(e1, e2, w, lp1ref, lp2ref, pref, out);
}

// round 15
// speedup vs baseline: 1.0021x; 1.0021x over previous
#include <cuda_runtime.h>
#include <math.h>

#define BB 32
#define SS 2048
#define DD 1024
#define ROWS 64
#define CHUNKS (SS / ROWS)      // 32 blocks per batch
#define NBLK (BB * CHUNKS)      // 1024 blocks — single wave
#define BETA_F 0.1f
#define RHO_F 1.0f
#define CNT_STRIDE 32           // pad counters to 128B

// Deterministic per-block partials, packed: .x = <e1,w>, .y = <e2,w>
__device__ float2 g_p[NBLK];
// Per-batch completion counters (zero at load; epilogue resets each replay)
__device__ unsigned int g_cnt[BB * CNT_STRIDE];

// ---------------- hot streaming kernel — STANDALONE (the only thing that
// keeps it at 7 TB/s; every attempt to merge epilogue code in cost 8-15us) ----
__global__ void __launch_bounds__(256) wdpo_reduce(const float* __restrict__ e1,
                                                   const float* __restrict__ e2,
                                                   const float* __restrict__ w) {
    const int t   = threadIdx.x;            // 0..255, owns float4 column group
    const int blk = blockIdx.x;
    const int b     = blk >> 5;             // / CHUNKS
    const int chunk = blk & (CHUNKS - 1);

    const float4 w4 = reinterpret_cast<const float4*>(w)[t];

    const size_t base = ((size_t)b * SS + (size_t)chunk * ROWS) * DD + 4 * (size_t)t;
    const float4* __restrict__ p1 = reinterpret_cast<const float4*>(e1 + base);
    const float4* __restrict__ p2 = reinterpret_cast<const float4*>(e2 + base);

    float s1 = 0.f, s2 = 0.f;
#pragma unroll 8
    for (int r = 0; r < ROWS; r++) {
        const float4 a = p1[(size_t)r * (DD / 4)];
        const float4 c = p2[(size_t)r * (DD / 4)];
        s1 += a.x * w4.x + a.y * w4.y + a.z * w4.z + a.w * w4.w;
        s2 += c.x * w4.x + c.y * w4.y + c.z * w4.z + c.w * w4.w;
    }

    // block reduction: warp shuffle then 8-warp shared fold
    __shared__ float sh1[8], sh2[8];
#pragma unroll
    for (int o = 16; o; o >>= 1) {
        s1 += __shfl_down_sync(0xffffffffu, s1, o);
        s2 += __shfl_down_sync(0xffffffffu, s2, o);
    }
    const int lane = t & 31, wid = t >> 5;
    if (lane == 0) { sh1[wid] = s1; sh2[wid] = s2; }
    __syncthreads();
    if (wid == 0) {
        s1 = (lane < 8) ? sh1[lane] : 0.f;
        s2 = (lane < 8) ? sh2[lane] : 0.f;
#pragma unroll
        for (int o = 4; o; o >>= 1) {
            s1 += __shfl_down_sync(0xffffffffu, s1, o);
            s2 += __shfl_down_sync(0xffffffffu, s2, o);
        }
        if (lane == 0) {
            // single-thread release + per-batch flag (R9-measured: full speed)
            g_p[blk] = make_float2(s1, s2);
            __threadfence();
            atomicAdd(&g_cnt[b * CNT_STRIDE], 1u);
        }
    }
}

// ---------------- concurrent epilogue: sibling graph node, spin-folds ---------
__global__ void __launch_bounds__(256) wdpo_epilogue(const float* __restrict__ w,
                                                     const float* __restrict__ lp1ref,
                                                     const float* __restrict__ lp2ref,
                                                     const float* __restrict__ pref,
                                                     float* __restrict__ out) {
    const int t = threadIdx.x;
    const int lane = t & 31, wid = t >> 5;

    __shared__ float sh[8];
    __shared__ float s_ind[BB];
    __shared__ float s_c2[BB];
    __shared__ float s_wsq;

    // ||w||^2 while the reduce streams on the other SMs (w = 4KB)
    {
        const float4 wv = reinterpret_cast<const float4*>(w)[t];
        float v = wv.x * wv.x + wv.y * wv.y + wv.z * wv.z + wv.w * wv.w;
#pragma unroll
        for (int o = 16; o; o >>= 1) v += __shfl_down_sync(0xffffffffu, v, o);
        if (lane == 0) sh[wid] = v;
        __syncthreads();
        if (t == 0) {
            float a = 0.f;
#pragma unroll
            for (int i = 0; i < 8; i++) a += sh[i];
            s_wsq = a;
        }
    }

    // warp `wid` owns batches wid*4 .. wid*4+3: wait each batch's 32 flags,
    // fold its 32 partials (one float2 per lane). Early batches fold while
    // late ones still stream — only the last fold is exposed.
#pragma unroll
    for (int j = 0; j < 4; j++) {
        const int bb = wid * 4 + j;
        unsigned int* cnt = &g_cnt[bb * CNT_STRIDE];
        if (lane == 0) {
            while (atomicAdd(cnt, 0u) < (unsigned)CHUNKS) __nanosleep(128);
        }
        __syncwarp();
        __threadfence();                            // acquire partials

        const float2 pp = __ldcg(&g_p[bb * CHUNKS + lane]);
        float s1 = pp.x, s2 = pp.y;
#pragma unroll
        for (int o = 16; o; o >>= 1) {
            s1 += __shfl_down_sync(0xffffffffu, s1, o);
            s2 += __shfl_down_sync(0xffffffffu, s2, o);
        }
        if (lane == 0) {
            const float h = (s1 - lp1ref[bb]) - (s2 - lp2ref[bb]);
            const float z = BETA_F * h;
            const float p = pref[bb];
            // stable softplus: softplus(x) = max(x,0) + log1p(exp(-|x|))
            const float lp = log1pf(expf(-fabsf(z)));
            const float sp_pos = fmaxf(z, 0.f) + lp;   // softplus(z)  = l2
            const float sp_neg = fmaxf(-z, 0.f) + lp;  // softplus(-z) = l1
            s_ind[bb] = p * sp_neg + (1.f - p) * sp_pos;
            const float sig = 1.f / (1.f + expf(-z));
            const float c = BETA_F * (sig - p);
            s_c2[bb] = c * c;                           // wsq factored out
            *cnt = 0u;                                  // reset for next replay
        }
    }
    __syncthreads();
    if (wid == 0) {
        float i  = s_ind[lane];
        float c2 = s_c2[lane];
#pragma unroll
        for (int o = 16; o; o >>= 1) {
            i  += __shfl_down_sync(0xffffffffu, i, o);
            c2 += __shfl_down_sync(0xffffffffu, c2, o);
        }
        if (lane == 0) {
            // mean(gns) = 2*S*wsq*mean(c^2)
            out[0] = i * (1.f / (float)BB)
                   + RHO_F * sqrtf(2.f * (float)SS * s_wsq * c2 * (1.f / (float)BB));
        }
    }
}

extern "C" void kernel_launch(void* const* d_in, const int* in_sizes, int n_in,
                              void* d_out, int out_size) {
    const float* e1     = (const float*)d_in[0];  // emb_a1 (B,S,D)
    const float* e2     = (const float*)d_in[1];  // emb_a2 (B,S,D)
    const float* w      = (const float*)d_in[2];  // w (D,)
    const float* lp1ref = (const float*)d_in[3];  // log_prob_a1_ref (B,)
    const float* lp2ref = (const float*)d_in[4];  // log_prob_a2_ref (B,)
    const float* pref   = (const float*)d_in[5];  // preference (B,)
    float* out          = (float*)d_out;

    // Lazily created host-side objects (no device memory — legal).
    static cudaStream_t s2 = nullptr;
    static cudaEvent_t evFork = nullptr, evJoin = nullptr;
    if (s2 == nullptr) {
        if (cudaStreamCreateWithFlags(&s2, cudaStreamNonBlocking) != cudaSuccess) s2 = nullptr;
        if (s2) {
            cudaEventCreateWithFlags(&evFork, cudaEventDisableTiming);
            cudaEventCreateWithFlags(&evJoin, cudaEventDisableTiming);
        }
    }

    if (s2) {
        // Fork BEFORE the reduce launch: the epilogue becomes a SIBLING graph
        // node (no dependency on the reduce) and runs concurrently, using the
        // device flag protocol for synchronization.
        cudaEventRecord(evFork, 0);
        cudaStreamWaitEvent(s2, evFork, 0);

        wdpo_reduce<<<NBLK, 256>>>(e1, e2, w);
        wdpo_epilogue<<<1, 256, 0, s2>>>(w, lp1ref, lp2ref, pref, out);

        cudaEventRecord(evJoin, s2);
        cudaStreamWaitEvent(0, evJoin, 0);
    } else {
        // Fallback: serial two-kernel (R12 behavior, flag protocol still correct)
        wdpo_reduce<<<NBLK, 256>>>(e1, e2, w);
        wdpo_epilogue<<<1, 256>>>(w, lp1ref, lp2ref, pref, out);
    }
}

// round 16
// speedup vs baseline: 1.0835x; 1.0812x over previous
#include <cuda_runtime.h>
#include <math.h>

#define BB 32
#define SS 2048
#define DD 1024
#define ROWS 16
#define CHUNKS (SS / ROWS)      // 128 blocks per batch
#define NBLK (BB * CHUNKS)      // 4096 blocks total (R7 shape: best measured)
#define BETA_F 0.1f
#define RHO_F 1.0f

// Deterministic per-block partials, packed: .x = <e1,w>, .y = <e2,w>
// 16B-aligned so the epilogue can fold with float4 loads.
__device__ __align__(16) float2 g_p[NBLK];
__device__ float g_wsq;         // ||w||^2, produced by reduce block 0

// ---------------- hot streaming kernel — STANDALONE, R7 body verbatim ---------
__global__ void __launch_bounds__(256) wdpo_reduce(const float* __restrict__ e1,
                                                   const float* __restrict__ e2,
                                                   const float* __restrict__ w) {
    const int t   = threadIdx.x;            // 0..255, owns float4 column group
    const int blk = blockIdx.x;
    const int b     = blk >> 7;             // / CHUNKS
    const int chunk = blk & (CHUNKS - 1);

    const float4 w4 = reinterpret_cast<const float4*>(w)[t];

    const size_t base = ((size_t)b * SS + (size_t)chunk * ROWS) * DD + 4 * (size_t)t;
    const float4* __restrict__ p1 = reinterpret_cast<const float4*>(e1 + base);
    const float4* __restrict__ p2 = reinterpret_cast<const float4*>(e2 + base);

    float s1 = 0.f, s2 = 0.f;
#pragma unroll 8
    for (int r = 0; r < ROWS; r++) {
        const float4 a = p1[(size_t)r * (DD / 4)];
        const float4 c = p2[(size_t)r * (DD / 4)];
        s1 += a.x * w4.x + a.y * w4.y + a.z * w4.z + a.w * w4.w;
        s2 += c.x * w4.x + c.y * w4.y + c.z * w4.z + c.w * w4.w;
    }

    // block reduction: warp shuffle then 8-warp shared fold
    __shared__ float sh1[8], sh2[8];
#pragma unroll
    for (int o = 16; o; o >>= 1) {
        s1 += __shfl_down_sync(0xffffffffu, s1, o);
        s2 += __shfl_down_sync(0xffffffffu, s2, o);
    }
    const int lane = t & 31, wid = t >> 5;
    if (lane == 0) { sh1[wid] = s1; sh2[wid] = s2; }
    __syncthreads();
    if (wid == 0) {
        s1 = (lane < 8) ? sh1[lane] : 0.f;
        s2 = (lane < 8) ? sh2[lane] : 0.f;
#pragma unroll
        for (int o = 4; o; o >>= 1) {
            s1 += __shfl_down_sync(0xffffffffu, s1, o);
            s2 += __shfl_down_sync(0xffffffffu, s2, o);
        }
        if (lane == 0) g_p[blk] = make_float2(s1, s2);
    }

    // Block 0 also produces ||w||^2 from its resident w4 regs (R12: neutral cost)
    if (blk == 0) {
        __syncthreads();
        float v = w4.x * w4.x + w4.y * w4.y + w4.z * w4.z + w4.w * w4.w;
#pragma unroll
        for (int o = 16; o; o >>= 1) v += __shfl_down_sync(0xffffffffu, v, o);
        if (lane == 0) sh1[wid] = v;
        __syncthreads();
        if (t == 0) {
            float a = 0.f;
#pragma unroll
            for (int i = 0; i < 8; i++) a += sh1[i];
            g_wsq = a;
        }
    }

    cudaTriggerProgrammaticLaunchCompletion();
}

// ---------------- single-warp, barrier-free epilogue --------------------------
// Lane b owns batch b: folds its 128 partials (64 float4 loads, all
// independent), computes its own scalar math in parallel, then one shuffle
// fold. No __syncthreads, no shared staging, no lane-0 serialization.
__global__ void __launch_bounds__(32) wdpo_epilogue(const float* __restrict__ lp1ref,
                                                    const float* __restrict__ lp2ref,
                                                    const float* __restrict__ pref,
                                                    float* __restrict__ out) {
    const int b = threadIdx.x;              // 0..31: one batch per lane

    cudaGridDependencySynchronize();        // partials + g_wsq ready

    // fold 128 partials = 64 float4 (two float2 each), independent loads
    const float4* __restrict__ pp = reinterpret_cast<const float4*>(&g_p[b * CHUNKS]);
    float s1 = 0.f, s2 = 0.f;
#pragma unroll 16
    for (int c = 0; c < CHUNKS / 2; c++) {
        const float4 v = __ldcg(&pp[c]);
        s1 += v.x + v.z;
        s2 += v.y + v.w;
    }

    // per-lane scalar math (parallel across all 32 batches)
    const float h = (s1 - lp1ref[b]) - (s2 - lp2ref[b]);
    const float z = BETA_F * h;
    const float p = pref[b];
    // stable softplus: softplus(x) = max(x,0) + log1p(exp(-|x|))
    const float lp = log1pf(expf(-fabsf(z)));
    const float sp_pos = fmaxf(z, 0.f) + lp;   // softplus(z)  = l2
    const float sp_neg = fmaxf(-z, 0.f) + lp;  // softplus(-z) = l1
    float ind = p * sp_neg + (1.f - p) * sp_pos;
    const float sig = 1.f / (1.f + expf(-z));
    const float c = BETA_F * (sig - p);
    float c2 = c * c;

    // one warp fold for both sums
#pragma unroll
    for (int o = 16; o; o >>= 1) {
        ind += __shfl_down_sync(0xffffffffu, ind, o);
        c2  += __shfl_down_sync(0xffffffffu, c2, o);
    }
    if (b == 0) {
        // mean(gns) = 2*S*wsq*mean(c^2)
        out[0] = ind * (1.f / (float)BB)
               + RHO_F * sqrtf(2.f * (float)SS * g_wsq * c2 * (1.f / (float)BB));
    }
}

extern "C" void kernel_launch(void* const* d_in, const int* in_sizes, int n_in,
                              void* d_out, int out_size) {
    const float* e1     = (const float*)d_in[0];  // emb_a1 (B,S,D)
    const float* e2     = (const float*)d_in[1];  // emb_a2 (B,S,D)
    const float* w      = (const float*)d_in[2];  // w (D,)
    const float* lp1ref = (const float*)d_in[3];  // log_prob_a1_ref (B,)
    const float* lp2ref = (const float*)d_in[4];  // log_prob_a2_ref (B,)
    const float* pref   = (const float*)d_in[5];  // preference (B,)
    float* out          = (float*)d_out;

    wdpo_reduce<<<NBLK, 256>>>(e1, e2, w);

    // Serial dependent epilogue with PDL attr (R7: best measured arrangement)
    cudaLaunchConfig_t cfg = {};
    cfg.gridDim  = dim3(1, 1, 1);
    cfg.blockDim = dim3(32, 1, 1);
    cfg.dynamicSmemBytes = 0;
    cfg.stream = 0;
    cudaLaunchAttribute attr[1];
    attr[0].id = cudaLaunchAttributeProgrammaticStreamSerialization;
    attr[0].val.programmaticStreamSerializationAllowed = 1;
    cfg.attrs = attr;
    cfg.numAttrs = 1;
    cudaError_t err = cudaLaunchKernelEx(&cfg, wdpo_epilogue, lp1ref, lp2ref, pref, out);
    if (err != cudaSuccess) {
        wdpo_epilogue<<<1, 32>>>(lp1ref, lp2ref, pref, out);
    }
}

// round 17
// speedup vs baseline: 1.1194x; 1.0332x over previous
#include <cuda_runtime.h>
#include <math.h>

#define BB 32
#define SS 2048
#define DD 1024
#define ROWS 16
#define CHUNKS (SS / ROWS)      // 128 blocks per batch
#define NBLK (BB * CHUNKS)      // 4096 blocks total
#define BETA_F 0.1f
#define RHO_F 1.0f

// Deterministic per-block partials (no float atomics -> bitwise stable across replays)
__device__ float g_p1[NBLK];
__device__ float g_p2[NBLK];

// ---------------- hot streaming kernel: standalone, measured 7.0 TB/s ---------
__global__ void __launch_bounds__(256) wdpo_reduce(const float* __restrict__ e1,
                                                   const float* __restrict__ e2,
                                                   const float* __restrict__ w) {
    const int t   = threadIdx.x;            // 0..255, owns float4 column group
    const int blk = blockIdx.x;
    const int b     = blk >> 7;             // / CHUNKS
    const int chunk = blk & (CHUNKS - 1);

    // each thread keeps its 4 w values in registers for the whole block
    const float4 w4 = reinterpret_cast<const float4*>(w)[t];

    const size_t base = ((size_t)b * SS + (size_t)chunk * ROWS) * DD + 4 * (size_t)t;
    const float4* __restrict__ p1 = reinterpret_cast<const float4*>(e1 + base);
    const float4* __restrict__ p2 = reinterpret_cast<const float4*>(e2 + base);

    float s1 = 0.f, s2 = 0.f;
#pragma unroll 8
    for (int r = 0; r < ROWS; r++) {
        const float4 a = p1[(size_t)r * (DD / 4)];
        const float4 c = p2[(size_t)r * (DD / 4)];
        s1 += a.x * w4.x + a.y * w4.y + a.z * w4.z + a.w * w4.w;
        s2 += c.x * w4.x + c.y * w4.y + c.z * w4.z + c.w * w4.w;
    }

    // block reduction: warp shuffle then 8-warp shared fold
    __shared__ float sh1[8], sh2[8];
#pragma unroll
    for (int o = 16; o; o >>= 1) {
        s1 += __shfl_down_sync(0xffffffffu, s1, o);
        s2 += __shfl_down_sync(0xffffffffu, s2, o);
    }
    const int lane = t & 31, wid = t >> 5;
    if (lane == 0) { sh1[wid] = s1; sh2[wid] = s2; }
    __syncthreads();
    if (wid == 0) {
        s1 = (lane < 8) ? sh1[lane] : 0.f;
        s2 = (lane < 8) ? sh2[lane] : 0.f;
#pragma unroll
        for (int o = 4; o; o >>= 1) {
            s1 += __shfl_down_sync(0xffffffffu, s1, o);
            s2 += __shfl_down_sync(0xffffffffu, s2, o);
        }
        if (lane == 0) { g_p1[blk] = s1; g_p2[blk] = s2; }
    }

    // PDL: committed; dependent epilogue may begin launching.
    cudaTriggerProgrammaticLaunchCompletion();
}

// ---------------- epilogue: primary-independent work BEFORE the dependency ----
__global__ void __launch_bounds__(1024) wdpo_epilogue(const float* __restrict__ w,
                                                      const float* __restrict__ lp1ref,
                                                      const float* __restrict__ lp2ref,
                                                      const float* __restrict__ pref,
                                                      float* __restrict__ out) {
    const int t = threadIdx.x;
    const int lane = t & 31, wid = t >> 5;

    __shared__ float swsq[32];
    __shared__ float s_ind[32];
    __shared__ float s_gns[32];

    // ||w||^2 — reads only the kernel INPUT w; overlaps with the reduce tail
    // under PDL when honored.
    float v = w[t];
    v = v * v;
#pragma unroll
    for (int o = 16; o; o >>= 1) v += __shfl_down_sync(0xffffffffu, v, o);
    if (lane == 0) swsq[wid] = v;
    __syncthreads();
    if (t == 0) {
        float a = 0.f;
#pragma unroll
        for (int i = 0; i < 32; i++) a += swsq[i];
        swsq[0] = a;
    }
    __syncthreads();
    const float wsq = swsq[0];

    // Wait for the primary grid (all partials written & visible).
    cudaGridDependencySynchronize();

    // warp `wid` folds the 128 partials of batch b = wid (deterministic order)
    const int b = wid;
    const int base = b * CHUNKS;
    float s1 = g_p1[base + lane] + g_p1[base + lane + 32] +
               g_p1[base + lane + 64] + g_p1[base + lane + 96];
    float s2 = g_p2[base + lane] + g_p2[base + lane + 32] +
               g_p2[base + lane + 64] + g_p2[base + lane + 96];
#pragma unroll
    for (int o = 16; o; o >>= 1) {
        s1 += __shfl_down_sync(0xffffffffu, s1, o);
        s2 += __shfl_down_sync(0xffffffffu, s2, o);
    }
    if (lane == 0) {
        const float h = (s1 - lp1ref[b]) - (s2 - lp2ref[b]);
        const float z = BETA_F * h;
        const float p = pref[b];
        // stable softplus: softplus(x) = max(x,0) + log1p(exp(-|x|))
        const float lp = log1pf(expf(-fabsf(z)));
        const float sp_pos = fmaxf(z, 0.f) + lp;   // softplus(z)  = l2
        const float sp_neg = fmaxf(-z, 0.f) + lp;  // softplus(-z) = l1
        const float ind = p * sp_neg + (1.f - p) * sp_pos;
        const float sig = 1.f / (1.f + expf(-z));
        const float c = BETA_F * (sig - p);
        s_ind[b] = ind;
        s_gns[b] = 2.f * (float)SS * wsq * c * c;
    }
    __syncthreads();
    if (wid == 0) {
        float i = s_ind[lane];
        float g = s_gns[lane];
#pragma unroll
        for (int o = 16; o; o >>= 1) {
            i += __shfl_down_sync(0xffffffffu, i, o);
            g += __shfl_down_sync(0xffffffffu, g, o);
        }
        if (lane == 0) out[0] = i * (1.f / (float)BB) + RHO_F * sqrtf(g * (1.f / (float)BB));
    }
}

extern "C" void kernel_launch(void* const* d_in, const int* in_sizes, int n_in,
                              void* d_out, int out_size) {
    const float* e1     = (const float*)d_in[0];  // emb_a1 (B,S,D)
    const float* e2     = (const float*)d_in[1];  // emb_a2 (B,S,D)
    const float* w      = (const float*)d_in[2];  // w (D,)
    const float* lp1ref = (const float*)d_in[3];  // log_prob_a1_ref (B,)
    const float* lp2ref = (const float*)d_in[4];  // log_prob_a2_ref (B,)
    const float* pref   = (const float*)d_in[5];  // preference (B,)
    float* out          = (float*)d_out;

    wdpo_reduce<<<NBLK, 256>>>(e1, e2, w);

    // Epilogue with programmatic dependent launch attr (best-measured tail).
    cudaLaunchConfig_t cfg = {};
    cfg.gridDim  = dim3(1, 1, 1);
    cfg.blockDim = dim3(1024, 1, 1);
    cfg.dynamicSmemBytes = 0;
    cfg.stream = 0;
    cudaLaunchAttribute attr[1];
    attr[0].id = cudaLaunchAttributeProgrammaticStreamSerialization;
    attr[0].val.programmaticStreamSerializationAllowed = 1;
    cfg.attrs = attr;
    cfg.numAttrs = 1;
    cudaError_t err = cudaLaunchKernelEx(&cfg, wdpo_epilogue, w, lp1ref, lp2ref, pref, out);
    if (err != cudaSuccess) {
        // Fallback: plain launch (identical semantics, no overlap)
        wdpo_epilogue<<<1, 1024>>>(w, lp1ref, lp2ref, pref, out);
    }
}